// round 16
// baseline (speedup 1.0000x reference)
#include <cuda_runtime.h>

#define NN 50000
#define BB 8
#define BN (BB*NN)
#define DD 64
#define HISTLEN 50
#define NW ((NN+31)/32)
#define L1_CAP (1<<16)
#define CH_CAP (1<<23)       /* >= 8*E for E<=1M */

// ---------------- static device scratch ----------------
__device__ float g_cl, g_cr, g_el0, g_er0;
__device__ float g_wal[DD], g_war[DD], g_h0[DD], g_H0[DD], g_G1[DD], g_G0[DD];

__device__ unsigned g_code[NN];
__device__ int      g_deg[NN];
__device__ unsigned g_mask[NN];
__device__ unsigned g_bm1[NW];
__device__ unsigned g_bm2[NW];
__device__ unsigned g_counts[BN];   // index v*8+b  (scan1 locality)
__device__ float    g_dphir[BN];    // index b*NN+v (final balance)
__device__ int      g_idxK[BN];     // index b*NN+v
__device__ int      g_head[BN];     // index b*NN+v
__device__ int      g_l1[L1_CAP];   // compact list of special (v*8+b)
__device__ float    g_philc[L1_CAP];
__device__ float    g_H2c[(size_t)L1_CAP*DD];
__device__ unsigned long long g_ch[CH_CAP];  // packed (k<<32)|next
__device__ int g_ctrL1, g_deg0;

__device__ __forceinline__ float leakyf(float x){ return x > 0.f ? x : 0.2f*x; }

// ---------------- K0: scatter + constants only (zeroing done by memset DMA) ----------------
__global__ void k_prep(const int* __restrict__ hist, const int* __restrict__ exits, int n_exits,
                       const float* __restrict__ W1, const float* __restrict__ al1,
                       const float* __restrict__ ar1, const float* __restrict__ b1,
                       const float* __restrict__ W2, const float* __restrict__ al2,
                       const float* __restrict__ ar2, const float* __restrict__ b2){
    int tid = threadIdx.x;
    if (blockIdx.x == 0){
        for (int i = tid; i < BB*n_exits; i += 256){
            int b = i / n_exits; int v = exits[i - b*n_exits];
            atomicOr(&g_code[v], 1u << (4*b));
            atomicOr(&g_bm1[v >> 5], 1u << (v & 31));
        }
        __syncthreads();
        for (int i = tid; i < BB*(HISTLEN-1); i += 256){
            int b = i / (HISTLEN-1); int j = i - b*(HISTLEN-1);
            int v = hist[b*HISTLEN + j]; int sh = 4*b;
            atomicAnd(&g_code[v], ~(0xFu << sh));
            atomicOr (&g_code[v], 2u << sh);
            atomicOr (&g_bm1[v >> 5], 1u << (v & 31));
        }
        __syncthreads();
        if (tid < BB){
            int v = hist[tid*HISTLEN + HISTLEN-1]; int sh = 4*tid;
            atomicAnd(&g_code[v], ~(0xFu << sh));
            atomicOr (&g_code[v], 3u << sh);
            atomicOr (&g_bm1[v >> 5], 1u << (v & 31));
        }
    } else {
        if (tid < DD){
            float wl = 0.f, wr = 0.f;
            for (int j = 0; j < DD; j++){ float w = W2[tid*DD + j]; wl += w*al2[j]; wr += w*ar2[j]; }
            g_wal[tid] = wl; g_war[tid] = wr;
            g_h0[tid] = fmaxf(b1[tid], 0.f);
        }
        __syncthreads();
        if (tid < DD){
            float h = 0.f;
            for (int j = 0; j < DD; j++) h += g_h0[j]*W2[j*DD + tid];
            g_H0[tid] = h;
            g_G1[tid] = fmaxf(h + b2[tid], 0.f);
            g_G0[tid] = fmaxf(b2[tid], 0.f);
        }
        if (tid == 0){
            float cl = 0.f, cr = 0.f;
            for (int j = 0; j < DD; j++){ cl += W1[j]*al1[j]; cr += W1[j]*ar1[j]; }
            g_cl = cl; g_cr = cr;
        }
        __syncthreads();
        if (tid == 0){
            float el = 0.f, er = 0.f;
            for (int j = 0; j < DD; j++){ el += g_h0[j]*g_wal[j]; er += g_h0[j]*g_war[j]; }
            g_el0 = el; g_er0 = er;
        }
        if (tid == 32){ g_ctrL1 = 0; g_deg0 = 0; }
    }
}

// ---------------- K1: edge scan 1 (int4 4 edges/thread, NO barriers, rare direct pushes) ----------------
__global__ void k_scan1(const int* __restrict__ src, const int* __restrict__ dst, int E){
    __shared__ unsigned sbm[NW];
    int tid = threadIdx.x;
    for (int i = tid; i < NW; i += 256) sbm[i] = g_bm1[i];
    __syncthreads();
    int t4 = blockIdx.x*256 + tid;
    int base = t4 << 2;
    int svA[4], dvA[4];
    int nEdge = 0;
    if (base + 3 < E){
        int4 sv = __ldg((const int4*)src + t4);
        int4 dv = __ldg((const int4*)dst + t4);
        svA[0]=sv.x; svA[1]=sv.y; svA[2]=sv.z; svA[3]=sv.w;
        dvA[0]=dv.x; dvA[1]=dv.y; dvA[2]=dv.z; dvA[3]=dv.w;
        nEdge = 4;
    } else {
        for (int j = base; j < E; j++){ svA[nEdge]=__ldg(&src[j]); dvA[nEdge]=__ldg(&dst[j]); nEdge++; }
    }
    for (int c = 0; c < nEdge; c++) atomicAdd(&g_deg[dvA[c]], 1);
    for (int c = 0; c < nEdge; c++){
        int sv = svA[c], dv = dvA[c];
        if ((sbm[sv >> 5] >> (sv & 31)) & 1u){
            unsigned cc = g_code[sv];
            while (cc){
                int bit = __ffs(cc) - 1;
                int b   = bit >> 2;
                unsigned cls = (cc >> (4*b)) & 0xFu;
                cc &= ~(0xFu << (4*b));
                int i2 = dv*BB + b;
                unsigned old = atomicAdd(&g_counts[i2], 1u << (10*(cls-1)));
                if (old == 0u){              // first touch: rare
                    int p = atomicAdd(&g_ctrL1, 1);
                    if (p < L1_CAP) g_l1[p] = i2;
                }
            }
        }
    }
}

// ---------------- K2: list-driven per-slot compute (warp/entry, even balance) ----------------
__global__ void k_prep2(const float* __restrict__ W1, const float* __restrict__ b1,
                        const float* __restrict__ W2){
    __shared__ float sW2[DD*DD];
    __shared__ float sh1[8][DD];
    __shared__ float scst[4*DD];
    int tid = threadIdx.x;
    {   // deg0
        int g = blockIdx.x*256 + tid;
        int gs = gridDim.x*256;
        int cnt = 0;
        for (int v = g; v < NN; v += gs) if (g_deg[v] == 0) cnt++;
        #pragma unroll
        for (int o = 16; o; o >>= 1) cnt += __shfl_xor_sync(0xffffffffu, cnt, o);
        if ((tid & 31) == 0 && cnt) atomicAdd(&g_deg0, cnt);
    }
    for (int j = tid; j < DD*DD; j += 256) sW2[j] = W2[j];
    if (tid < DD){
        scst[tid]        = W1[tid];
        scst[DD + tid]   = b1[tid];
        scst[2*DD + tid] = g_wal[tid];
        scst[3*DD + tid] = g_war[tid];
    }
    __syncthreads();

    int K = g_ctrL1; if (K > L1_CAP) K = L1_CAP;
    int wid = tid >> 5, lane = tid & 31;
    int gwarp = blockIdx.x*8 + wid, nwarp = gridDim.x*8;
    float er0 = g_er0, cl = g_cl, cr = g_cr;
    for (int e = gwarp; e < K; e += nwarp){
        int i2 = g_l1[e];
        int v = i2 >> 3, b = i2 & 7;
        unsigned c    = g_counts[i2];
        int      degv = g_deg[v];
        unsigned codev= g_code[v];
        int n1 = c & 1023, n2 = (c >> 10) & 1023, n3 = (c >> 20) & 1023;
        int n0 = degv - n1 - n2 - n3;
        unsigned clsv = (codev >> (4*b)) & 0xFu;
        float fd = (clsv == 0) ? 0.f : (clsv == 1 ? 1.0f : (clsv == 2 ? 0.1f : 0.5f));
        float crfd = cr*fd;
        int ln = lane & 3;
        float fL = (ln == 0) ? 0.f : (ln == 1 ? 1.0f : (ln == 2 ? 0.1f : 0.5f));
        int   nL = (ln == 0) ? n0  : (ln == 1 ? n1   : (ln == 2 ? n2   : n3));
        float wL = (float)nL * expf(leakyf(cl*fL + crfd));
        float numL = fL * wL;
        float den = wL + __shfl_xor_sync(0xffffffffu, wL, 1);
        den += __shfl_xor_sync(0xffffffffu, den, 2);
        float num = numL + __shfl_xor_sync(0xffffffffu, numL, 1);
        num += __shfl_xor_sync(0xffffffffu, num, 2);
        float s = num / den;
        float h0 = fmaxf(s*scst[lane]      + scst[DD + lane],      0.f);
        float h1 = fmaxf(s*scst[lane + 32] + scst[DD + lane + 32], 0.f);
        sh1[wid][lane] = h0; sh1[wid][lane + 32] = h1;
        float pl = h0*scst[2*DD + lane] + h1*scst[2*DD + lane + 32];
        float pr = h0*scst[3*DD + lane] + h1*scst[3*DD + lane + 32];
        #pragma unroll
        for (int o = 16; o; o >>= 1){
            pl += __shfl_xor_sync(0xffffffffu, pl, o);
            pr += __shfl_xor_sync(0xffffffffu, pr, o);
        }
        __syncwarp();
        if (lane == 0){
            g_philc[e] = pl;
            g_dphir[b*NN + v] = pr - er0;   // b-major
            g_idxK[b*NN + v]  = e;          // b-major
            atomicOr(&g_mask[v], 1u << b);
            atomicOr(&g_bm2[v >> 5], 1u << (v & 31));
        }
        float a0 = 0.f, a1 = 0.f;
        #pragma unroll 8
        for (int j = 0; j < DD; j++){
            float hv = sh1[wid][j];
            a0 += hv*sW2[j*DD + lane];
            a1 += hv*sW2[j*DD + lane + 32];
        }
        g_H2c[(size_t)e*DD + lane]      = a0;
        g_H2c[(size_t)e*DD + lane + 32] = a1;
        __syncwarp();
    }
}

// ---------------- K3: edge scan 2 (int4 4 edges/thread, NO barriers, packed chain) ----------------
__global__ void k_scan2(const int* __restrict__ src, const int* __restrict__ dst, int E){
    __shared__ unsigned sbm[NW];
    int tid = threadIdx.x;
    for (int i = tid; i < NW; i += 256) sbm[i] = g_bm2[i];
    __syncthreads();
    int t4 = blockIdx.x*256 + tid;
    int base = t4 << 2;
    int svA[4];
    int nEdge = 0;
    if (base + 3 < E){
        int4 sv = __ldg((const int4*)src + t4);
        svA[0]=sv.x; svA[1]=sv.y; svA[2]=sv.z; svA[3]=sv.w;
        nEdge = 4;
    } else {
        for (int j = base; j < E; j++){ svA[nEdge]=__ldg(&src[j]); nEdge++; }
    }
    for (int c = 0; c < nEdge; c++){
        int sv = svA[c];
        if ((sbm[sv >> 5] >> (sv & 31)) & 1u){
            unsigned m = __ldg(&g_mask[sv]);
            if (m){
                int ei = base + c;
                int dv = __ldg(&dst[ei]);
                do {
                    int b = __ffs(m) - 1; m &= m - 1;
                    int pos = (ei << 3) | b;           // unique, counter-free
                    if (pos < CH_CAP){
                        int k = __ldg(&g_idxK[b*NN + sv]);
                        int old = atomicExch(&g_head[b*NN + dv], pos);
                        g_ch[pos] = ((unsigned long long)(unsigned)k << 32) | (unsigned)old;
                    }
                } while (m);
            }
        }
    }
}

// ---------------- K4: dense ballot-scan over heads (b-major) -> chain walk + finalize ----------------
__global__ void k_final(float* out, const float* __restrict__ b2){
    __shared__ float sacc[BB][DD];
    int tid = threadIdx.x;
    int wid = tid >> 5, lane = tid & 31;
    const float inv = 1.0f / (float)NN;
    for (int j = tid; j < BB*DD; j += 256) ((float*)sacc)[j] = 0.f;
    __syncthreads();

    float er0 = g_er0, el0 = g_el0;
    float b2a = b2[lane], b2b = b2[lane + 32];
    float G1a = g_G1[lane], G1b = g_G1[lane + 32];
    float H0a = g_H0[lane], H0b = g_H0[lane + 32];

    int gwarp = blockIdx.x*8 + wid, nwarp = gridDim.x*8;
    int nChunk = (BN + 31) >> 5;
    for (int chk = gwarp; chk < nChunk; chk += nwarp){
        int i2 = chk*32 + lane;
        int head = (i2 < BN) ? g_head[i2] : -1;
        unsigned bal = __ballot_sync(0xffffffffu, head >= 0);
        while (bal){
            int l = __ffs(bal) - 1; bal &= bal - 1;
            int i2t = __shfl_sync(0xffffffffu, i2, l);
            int cur = __shfl_sync(0xffffffffu, head, l);
            int b = i2t / NN, v = i2t - b*NN;
            float dphir = g_dphir[i2t];
            float acc0 = 0.f, acc1 = 0.f, den = 0.f;
            int cnt = 0;
            while (cur >= 0){
                unsigned long long node = g_ch[cur];
                int k  = (int)(node >> 32);
                int nx = (int)(unsigned)(node & 0xffffffffu);
                float w = expf(leakyf(g_philc[k] + er0 + dphir));
                den += w; cnt++;
                const float* h2 = &g_H2c[(size_t)k*DD];
                acc0 += w*h2[lane];
                acc1 += w*h2[lane + 32];
                cur = nx;
            }
            int nb = g_deg[v] - cnt;
            if (nb > 0){
                float bw = (float)nb * expf(leakyf(el0 + er0 + dphir));
                den  += bw;
                acc0 += bw*H0a;
                acc1 += bw*H0b;
            }
            float rden = 1.0f / den;
            float v0 = fmaxf(acc0*rden + b2a, 0.f) - G1a;
            float v1 = fmaxf(acc1*rden + b2b, 0.f) - G1b;
            atomicAdd(&sacc[b][lane],      v0);
            atomicAdd(&sacc[b][lane + 32], v1);
        }
    }
    __syncthreads();
    for (int j = tid; j < BB*DD; j += 256){
        float a = ((float*)sacc)[j];
        if (a != 0.f) atomicAdd(&out[j], a*inv);
    }
    if (blockIdx.x == 0){
        int d0 = g_deg0;
        for (int j = tid; j < BB*DD; j += 256){
            int d = j & (DD-1);
            float cst = (float)(NN - d0)*g_G1[d] + (float)d0*g_G0[d];
            atomicAdd(&out[j], cst*inv);
        }
    }
}

// ---------------- launch ----------------
extern "C" void kernel_launch(void* const* d_in, const int* in_sizes, int n_in,
                              void* d_out, int out_size){
    const int*   hist  = (const int*)  d_in[0];
    const int*   exits = (const int*)  d_in[1];
    const int*   src   = (const int*)  d_in[2];
    const int*   dst   = (const int*)  d_in[3];
    const float* W1    = (const float*)d_in[4];
    const float* al1   = (const float*)d_in[5];
    const float* ar1   = (const float*)d_in[6];
    const float* b1    = (const float*)d_in[7];
    const float* W2    = (const float*)d_in[8];
    const float* al2   = (const float*)d_in[9];
    const float* ar2   = (const float*)d_in[10];
    const float* b2    = (const float*)d_in[11];
    float* out = (float*)d_out;
    int E   = in_sizes[2];
    int nex = in_sizes[1];

    // resolve device-symbol addresses once (host API, not captured)
    static bool s_init = false;
    static void *p_code, *p_deg, *p_mask, *p_bm1, *p_bm2, *p_counts, *p_dphir, *p_head;
    if (!s_init){
        cudaGetSymbolAddress(&p_code,   g_code);
        cudaGetSymbolAddress(&p_deg,    g_deg);
        cudaGetSymbolAddress(&p_mask,   g_mask);
        cudaGetSymbolAddress(&p_bm1,    g_bm1);
        cudaGetSymbolAddress(&p_bm2,    g_bm2);
        cudaGetSymbolAddress(&p_counts, g_counts);
        cudaGetSymbolAddress(&p_dphir,  g_dphir);
        cudaGetSymbolAddress(&p_head,   g_head);
        s_init = true;
    }

    // DMA zero/fill (graph-capturable)
    cudaMemsetAsync(p_counts, 0,    (size_t)BN*4);
    cudaMemsetAsync(p_dphir,  0,    (size_t)BN*4);
    cudaMemsetAsync(p_head,   0xFF, (size_t)BN*4);   // -1
    cudaMemsetAsync(p_code,   0,    (size_t)NN*4);
    cudaMemsetAsync(p_deg,    0,    (size_t)NN*4);
    cudaMemsetAsync(p_mask,   0,    (size_t)NN*4);
    cudaMemsetAsync(p_bm1,    0,    (size_t)NW*4);
    cudaMemsetAsync(p_bm2,    0,    (size_t)NW*4);
    cudaMemsetAsync(out,      0,    (size_t)BB*DD*4);

    int e4b = ((E + 3)/4 + 255) / 256;
    if (e4b < 1) e4b = 1;

    k_prep<<<2, 256>>>(hist, exits, nex, W1, al1, ar1, b1, W2, al2, ar2, b2);
    k_scan1<<<e4b, 256>>>(src, dst, E);
    k_prep2<<<512, 256>>>(W1, b1, W2);
    k_scan2<<<e4b, 256>>>(src, dst, E);
    k_final<<<1024, 256>>>(out, b2);
}

// round 17
// speedup vs baseline: 1.2609x; 1.2609x over previous
#include <cuda_runtime.h>

#define NN 50000
#define BB 8
#define BN (BB*NN)
#define DD 64
#define HISTLEN 50
#define NW ((NN+31)/32)
#define L1_CAP (1<<16)
#define CH_CAP (1<<23)       /* >= 8*E for E<=1M */
#define SCANT 512            /* scan block size */

// ---------------- static device scratch ----------------
__device__ float g_cl, g_cr, g_el0, g_er0;
__device__ float g_wal[DD], g_war[DD], g_h0[DD], g_H0[DD], g_G1[DD], g_G0[DD];

__device__ unsigned g_code[NN];
__device__ int      g_deg[NN];
__device__ unsigned g_mask[NN];
__device__ unsigned g_bm1[NW];
__device__ unsigned g_bm2[NW];
__device__ unsigned g_counts[BN];   // index v*8+b  (scan1 locality)
__device__ float    g_dphir[BN];    // index b*NN+v (final balance)
__device__ int      g_idxK[BN];     // index b*NN+v
__device__ int      g_head[BN];     // index b*NN+v
__device__ int      g_l1[L1_CAP];   // compact list of special (v*8+b)
__device__ float    g_philc[L1_CAP];
__device__ float    g_H2c[(size_t)L1_CAP*DD];
__device__ unsigned long long g_ch[CH_CAP];  // packed (k<<32)|next
__device__ int g_ctrL1, g_deg0;

__device__ __forceinline__ float leakyf(float x){ return x > 0.f ? x : 0.2f*x; }

// ---------------- K0: setup (zero + scatter + constants, one kernel) ----------------
__global__ void k_setup(const int* __restrict__ hist, const int* __restrict__ exits, int n_exits,
                        const float* __restrict__ W1, const float* __restrict__ al1,
                        const float* __restrict__ ar1, const float* __restrict__ b1,
                        const float* __restrict__ W2, const float* __restrict__ al2,
                        const float* __restrict__ ar2, const float* __restrict__ b2,
                        float* out){
    int tid = threadIdx.x, bid = blockIdx.x;
    if (bid == 0){
        for (int i = tid; i < NW; i += 256) g_bm1[i] = 0u;
        for (int i = tid; i < n_exits; i += 256) g_code[exits[i]] = 0u;
        for (int i = tid; i < BB*HISTLEN; i += 256) g_code[hist[i]] = 0u;
        __syncthreads();
        for (int i = tid; i < BB*n_exits; i += 256){
            int b = i / n_exits; int v = exits[i - b*n_exits];
            atomicOr(&g_code[v], 1u << (4*b));
            atomicOr(&g_bm1[v >> 5], 1u << (v & 31));
        }
        __syncthreads();
        for (int i = tid; i < BB*(HISTLEN-1); i += 256){
            int b = i / (HISTLEN-1); int j = i - b*(HISTLEN-1);
            int v = hist[b*HISTLEN + j]; int sh = 4*b;
            atomicAnd(&g_code[v], ~(0xFu << sh));
            atomicOr (&g_code[v], 2u << sh);
            atomicOr (&g_bm1[v >> 5], 1u << (v & 31));
        }
        __syncthreads();
        if (tid < BB){
            int v = hist[tid*HISTLEN + HISTLEN-1]; int sh = 4*tid;
            atomicAnd(&g_code[v], ~(0xFu << sh));
            atomicOr (&g_code[v], 3u << sh);
            atomicOr (&g_bm1[v >> 5], 1u << (v & 31));
        }
    } else if (bid == 1){
        if (tid < DD){
            float wl = 0.f, wr = 0.f;
            for (int j = 0; j < DD; j++){ float w = W2[tid*DD + j]; wl += w*al2[j]; wr += w*ar2[j]; }
            g_wal[tid] = wl; g_war[tid] = wr;
            g_h0[tid] = fmaxf(b1[tid], 0.f);
        }
        __syncthreads();
        if (tid < DD){
            float h = 0.f;
            for (int j = 0; j < DD; j++) h += g_h0[j]*W2[j*DD + tid];
            g_H0[tid] = h;
            g_G1[tid] = fmaxf(h + b2[tid], 0.f);
            g_G0[tid] = fmaxf(b2[tid], 0.f);
        }
        if (tid == 0){
            float cl = 0.f, cr = 0.f;
            for (int j = 0; j < DD; j++){ cl += W1[j]*al1[j]; cr += W1[j]*ar1[j]; }
            g_cl = cl; g_cr = cr;
        }
        __syncthreads();
        if (tid == 0){
            float el = 0.f, er = 0.f;
            for (int j = 0; j < DD; j++){ el += g_h0[j]*g_wal[j]; er += g_h0[j]*g_war[j]; }
            g_el0 = el; g_er0 = er;
        }
        if (tid == 32){ g_ctrL1 = 0; g_deg0 = 0; }
    } else {
        int g = (bid - 2)*256 + tid;
        int gs = (gridDim.x - 2)*256;
        for (int i = g; i < BN; i += gs){
            g_counts[i] = 0u; g_dphir[i] = 0.f; g_head[i] = -1;
        }
        for (int i = g; i < NN; i += gs){ g_deg[i] = 0; g_mask[i] = 0u; }
        for (int i = g; i < NW; i += gs) g_bm2[i] = 0u;
        if (g < BB*DD) out[g] = 0.f;
    }
}

// ---------------- K1: edge scan 1 (one edge/thread, 512-thr blocks, rare direct pushes) ----------------
__global__ void k_scan1(const int* __restrict__ src, const int* __restrict__ dst, int E){
    __shared__ unsigned sbm[NW];
    int tid = threadIdx.x;
    for (int i = tid; i < NW; i += SCANT) sbm[i] = g_bm1[i];
    __syncthreads();
    int i = blockIdx.x*SCANT + tid;
    if (i < E){
        int sv = __ldg(&src[i]);
        int dv = __ldg(&dst[i]);
        atomicAdd(&g_deg[dv], 1);
        if ((sbm[sv >> 5] >> (sv & 31)) & 1u){
            unsigned c = g_code[sv];
            while (c){
                int bit = __ffs(c) - 1;
                int b   = bit >> 2;
                unsigned cls = (c >> (4*b)) & 0xFu;
                c &= ~(0xFu << (4*b));
                int i2 = dv*BB + b;
                unsigned old = atomicAdd(&g_counts[i2], 1u << (10*(cls-1)));
                if (old == 0u){              // first touch: rare
                    int p = atomicAdd(&g_ctrL1, 1);
                    if (p < L1_CAP) g_l1[p] = i2;
                }
            }
        }
    }
}

// ---------------- K2: list-driven per-slot compute (warp/entry, even balance) ----------------
__global__ void k_prep2(const float* __restrict__ W1, const float* __restrict__ b1,
                        const float* __restrict__ W2){
    __shared__ float sW2[DD*DD];
    __shared__ float sh1[8][DD];
    __shared__ float scst[4*DD];
    int tid = threadIdx.x;
    {   // deg0
        int g = blockIdx.x*256 + tid;
        int gs = gridDim.x*256;
        int cnt = 0;
        for (int v = g; v < NN; v += gs) if (g_deg[v] == 0) cnt++;
        #pragma unroll
        for (int o = 16; o; o >>= 1) cnt += __shfl_xor_sync(0xffffffffu, cnt, o);
        if ((tid & 31) == 0 && cnt) atomicAdd(&g_deg0, cnt);
    }
    for (int j = tid; j < DD*DD; j += 256) sW2[j] = W2[j];
    if (tid < DD){
        scst[tid]        = W1[tid];
        scst[DD + tid]   = b1[tid];
        scst[2*DD + tid] = g_wal[tid];
        scst[3*DD + tid] = g_war[tid];
    }
    __syncthreads();

    int K = g_ctrL1; if (K > L1_CAP) K = L1_CAP;
    int wid = tid >> 5, lane = tid & 31;
    int gwarp = blockIdx.x*8 + wid, nwarp = gridDim.x*8;
    float er0 = g_er0, cl = g_cl, cr = g_cr;
    for (int e = gwarp; e < K; e += nwarp){
        int i2 = g_l1[e];
        int v = i2 >> 3, b = i2 & 7;
        unsigned c    = g_counts[i2];
        int      degv = g_deg[v];
        unsigned codev= g_code[v];
        int n1 = c & 1023, n2 = (c >> 10) & 1023, n3 = (c >> 20) & 1023;
        int n0 = degv - n1 - n2 - n3;
        unsigned clsv = (codev >> (4*b)) & 0xFu;
        float fd = (clsv == 0) ? 0.f : (clsv == 1 ? 1.0f : (clsv == 2 ? 0.1f : 0.5f));
        float crfd = cr*fd;
        int ln = lane & 3;
        float fL = (ln == 0) ? 0.f : (ln == 1 ? 1.0f : (ln == 2 ? 0.1f : 0.5f));
        int   nL = (ln == 0) ? n0  : (ln == 1 ? n1   : (ln == 2 ? n2   : n3));
        float wL = (float)nL * expf(leakyf(cl*fL + crfd));
        float numL = fL * wL;
        float den = wL + __shfl_xor_sync(0xffffffffu, wL, 1);
        den += __shfl_xor_sync(0xffffffffu, den, 2);
        float num = numL + __shfl_xor_sync(0xffffffffu, numL, 1);
        num += __shfl_xor_sync(0xffffffffu, num, 2);
        float s = num / den;
        float h0 = fmaxf(s*scst[lane]      + scst[DD + lane],      0.f);
        float h1 = fmaxf(s*scst[lane + 32] + scst[DD + lane + 32], 0.f);
        sh1[wid][lane] = h0; sh1[wid][lane + 32] = h1;
        float pl = h0*scst[2*DD + lane] + h1*scst[2*DD + lane + 32];
        float pr = h0*scst[3*DD + lane] + h1*scst[3*DD + lane + 32];
        #pragma unroll
        for (int o = 16; o; o >>= 1){
            pl += __shfl_xor_sync(0xffffffffu, pl, o);
            pr += __shfl_xor_sync(0xffffffffu, pr, o);
        }
        __syncwarp();
        if (lane == 0){
            g_philc[e] = pl;
            g_dphir[b*NN + v] = pr - er0;   // b-major
            g_idxK[b*NN + v]  = e;          // b-major
            atomicOr(&g_mask[v], 1u << b);
            atomicOr(&g_bm2[v >> 5], 1u << (v & 31));
        }
        float a0 = 0.f, a1 = 0.f;
        #pragma unroll 8
        for (int j = 0; j < DD; j++){
            float hv = sh1[wid][j];
            a0 += hv*sW2[j*DD + lane];
            a1 += hv*sW2[j*DD + lane + 32];
        }
        g_H2c[(size_t)e*DD + lane]      = a0;
        g_H2c[(size_t)e*DD + lane + 32] = a1;
        __syncwarp();
    }
}

// ---------------- K3: edge scan 2 (one edge/thread, 512-thr blocks, packed chain) ----------------
__global__ void k_scan2(const int* __restrict__ src, const int* __restrict__ dst, int E){
    __shared__ unsigned sbm[NW];
    int tid = threadIdx.x;
    for (int i = tid; i < NW; i += SCANT) sbm[i] = g_bm2[i];
    __syncthreads();
    int i = blockIdx.x*SCANT + tid;
    if (i < E){
        int sv = __ldg(&src[i]);
        if ((sbm[sv >> 5] >> (sv & 31)) & 1u){
            unsigned m = __ldg(&g_mask[sv]);
            if (m){
                int dv = __ldg(&dst[i]);
                do {
                    int b = __ffs(m) - 1; m &= m - 1;
                    int pos = (i << 3) | b;           // unique, counter-free
                    if (pos < CH_CAP){
                        int k = __ldg(&g_idxK[b*NN + sv]);
                        int old = atomicExch(&g_head[b*NN + dv], pos);
                        g_ch[pos] = ((unsigned long long)(unsigned)k << 32) | (unsigned)old;
                    }
                } while (m);
            }
        }
    }
}

// ---------------- K4: dense ballot-scan over heads (b-major) -> chain walk + finalize ----------------
__global__ void k_final(float* out, const float* __restrict__ b2){
    __shared__ float sacc[BB][DD];
    int tid = threadIdx.x;
    int wid = tid >> 5, lane = tid & 31;
    const float inv = 1.0f / (float)NN;
    for (int j = tid; j < BB*DD; j += 256) ((float*)sacc)[j] = 0.f;
    __syncthreads();

    float er0 = g_er0, el0 = g_el0;
    float b2a = b2[lane], b2b = b2[lane + 32];
    float G1a = g_G1[lane], G1b = g_G1[lane + 32];
    float H0a = g_H0[lane], H0b = g_H0[lane + 32];

    int gwarp = blockIdx.x*8 + wid, nwarp = gridDim.x*8;
    int nChunk = (BN + 31) >> 5;
    for (int chk = gwarp; chk < nChunk; chk += nwarp){
        int i2 = chk*32 + lane;
        int head = (i2 < BN) ? g_head[i2] : -1;
        unsigned bal = __ballot_sync(0xffffffffu, head >= 0);
        while (bal){
            int l = __ffs(bal) - 1; bal &= bal - 1;
            int i2t = __shfl_sync(0xffffffffu, i2, l);
            int cur = __shfl_sync(0xffffffffu, head, l);
            int b = i2t / NN, v = i2t - b*NN;
            float dphir = g_dphir[i2t];
            float acc0 = 0.f, acc1 = 0.f, den = 0.f;
            int cnt = 0;
            while (cur >= 0){
                unsigned long long node = g_ch[cur];
                int k  = (int)(node >> 32);
                int nx = (int)(unsigned)(node & 0xffffffffu);
                float w = expf(leakyf(g_philc[k] + er0 + dphir));
                den += w; cnt++;
                const float* h2 = &g_H2c[(size_t)k*DD];
                acc0 += w*h2[lane];
                acc1 += w*h2[lane + 32];
                cur = nx;
            }
            int nb = g_deg[v] - cnt;
            if (nb > 0){
                float bw = (float)nb * expf(leakyf(el0 + er0 + dphir));
                den  += bw;
                acc0 += bw*H0a;
                acc1 += bw*H0b;
            }
            float rden = 1.0f / den;
            float v0 = fmaxf(acc0*rden + b2a, 0.f) - G1a;
            float v1 = fmaxf(acc1*rden + b2b, 0.f) - G1b;
            atomicAdd(&sacc[b][lane],      v0);
            atomicAdd(&sacc[b][lane + 32], v1);
        }
    }
    __syncthreads();
    for (int j = tid; j < BB*DD; j += 256){
        float a = ((float*)sacc)[j];
        if (a != 0.f) atomicAdd(&out[j], a*inv);
    }
    if (blockIdx.x == 0){
        int d0 = g_deg0;
        for (int j = tid; j < BB*DD; j += 256){
            int d = j & (DD-1);
            float cst = (float)(NN - d0)*g_G1[d] + (float)d0*g_G0[d];
            atomicAdd(&out[j], cst*inv);
        }
    }
}

// ---------------- launch ----------------
extern "C" void kernel_launch(void* const* d_in, const int* in_sizes, int n_in,
                              void* d_out, int out_size){
    const int*   hist  = (const int*)  d_in[0];
    const int*   exits = (const int*)  d_in[1];
    const int*   src   = (const int*)  d_in[2];
    const int*   dst   = (const int*)  d_in[3];
    const float* W1    = (const float*)d_in[4];
    const float* al1   = (const float*)d_in[5];
    const float* ar1   = (const float*)d_in[6];
    const float* b1    = (const float*)d_in[7];
    const float* W2    = (const float*)d_in[8];
    const float* al2   = (const float*)d_in[9];
    const float* ar2   = (const float*)d_in[10];
    const float* b2    = (const float*)d_in[11];
    float* out = (float*)d_out;
    int E   = in_sizes[2];
    int nex = in_sizes[1];

    int eb = (E + SCANT - 1) / SCANT;
    if (eb < 1) eb = 1;

    k_setup<<<512, 256>>>(hist, exits, nex, W1, al1, ar1, b1, W2, al2, ar2, b2, out);
    k_scan1<<<eb, SCANT>>>(src, dst, E);
    k_prep2<<<512, 256>>>(W1, b1, W2);
    k_scan2<<<eb, SCANT>>>(src, dst, E);
    k_final<<<1024, 256>>>(out, b2);
}